// round 5
// baseline (speedup 1.0000x reference)
#include <cuda_runtime.h>

// Problem constants (fixed shapes)
#define BB   2
#define HD   4
#define HH   128
#define WW   128
#define KS   7
#define KK   49
#define NSP  9
#define SS   64
#define PLANE (HH * WW)

// Two pixels per warp: lanes 0-15 -> pixel (h,w0), lanes 16-31 -> (h,w0+1).
// Lane t (=lane&15) owns k in {t, t+16, t+32}; t==15 also owns k=48.
// 16-lane butterflies serve both pixels at once.
// No max-subtraction: softmax-style ratio is scale-invariant in exp().
__global__ __launch_bounds__(128, 8)
void attn_reweight_kernel(const float* __restrict__ attn,
                          const float* __restrict__ sims,
                          const int*   __restrict__ sinds,
                          float*       __restrict__ out)
{
    const int warpid = blockIdx.x * (blockDim.x >> 5) + (threadIdx.x >> 5);
    const int lane   = threadIdx.x & 31;
    const int half   = lane >> 4;
    const int t      = lane & 15;

    const int pix0 = warpid << 1;
    const int b    = pix0 >> 14;
    const int idx  = pix0 & 16383;
    const int h    = idx >> 7;
    const int w    = (idx & 127) + half;

    const int hs = min(max(h - KS / 2, 0), HH - KS);
    const int ws = min(max(w - KS / 2, 0), WW - KS);

    const int  k0 = t, k1 = t + 16, k2 = t + 32;
    const bool last = (t == 15);

    const int off0 = (hs + k0 / KS) * WW + ws + k0 % KS;
    const int off1 = (hs + k1 / KS) * WW + ws + k1 % KS;
    const int off2 = (hs + k2 / KS) * WW + ws + k2 % KS;
    const int off3 = (hs + 6) * WW + (ws + 6);          // k = 48

    // center index inside window (uniform per half-warp), source lane for pi shfl
    const int cidx = (h - hs) * KS + (w - ws);          // [0,48]
    const int srcl = ((cidx < 48) ? (cidx & 15) : 15) + (half << 4);

    const float* sb = sims + b * (SS * PLANE);

    // sinds: one coalesced load for both pixels (18 ints), distribute via shfl
    const int wb = pix0 * NSP;
    const int myind = (lane < 2 * NSP) ? __ldg(&sinds[wb + lane]) : 0;

    // ---- gather 9 planes ----
    float p0[NSP], p1v[NSP], p2[NSP], p3[NSP];
#pragma unroll
    for (int sp = 0; sp < NSP; ++sp) {
        const int gid = __shfl_sync(0xffffffffu, myind, sp + NSP * half);
        const float* pl = sb + gid * PLANE;
        p0[sp]  = __ldg(&pl[off0]);
        p1v[sp] = __ldg(&pl[off1]);
        p2[sp]  = __ldg(&pl[off2]);
        p3[sp]  = last ? __ldg(&pl[off3]) : 0.0f;
    }

    // ---- pi via shfl from the window (center is always inside) ----
    float pi[NSP];
#pragma unroll
    for (int sp = 0; sp < NSP; ++sp) {
        const float val = (cidx < 16) ? p0[sp]
                        : (cidx < 32) ? p1v[sp]
                        : (cidx < 48) ? p2[sp] : p3[sp];
        pi[sp] = __shfl_sync(0xffffffffu, val, srcl);
    }

    // ---- per-head compute ----
#pragma unroll
    for (int hd = 0; hd < HD; ++hd) {
        const int base = (((b * HD + hd) * HH + h) * WW + w) * KK;
        const float* ab = attn + base;

        const float av0 = __ldg(ab + k0);
        const float av1 = __ldg(ab + k1);
        const float av2 = __ldg(ab + k2);
        const float av3 = last ? __ldg(ab + 48) : -1e30f;

        // no max-subtraction needed: result is scale-invariant in exp
        const float a0 = __expf(av0);
        const float a1 = __expf(av1);
        const float a2 = __expf(av2);
        const float a3 = __expf(av3);   // exact 0 on non-last lanes

        // d[sp] = sum_k a_k * p_sp[k]  (16-lane butterfly)
        float d[NSP];
#pragma unroll
        for (int sp = 0; sp < NSP; ++sp) {
            float acc = fmaf(a0, p0[sp], a1 * p1v[sp]);
            acc = fmaf(a2, p2[sp], acc);
            acc = fmaf(a3, p3[sp], acc);
            d[sp] = acc;
        }
#pragma unroll
        for (int o = 8; o > 0; o >>= 1) {
#pragma unroll
            for (int sp = 0; sp < NSP; ++sp)
                d[sp] += __shfl_xor_sync(0xffffffffu, d[sp], o);
        }

        // w_sp = pi_sp / (eps + d_sp); paired reciprocals: 5 MUFU for 9 divides
        float wsp[NSP];
#pragma unroll
        for (int sp = 0; sp < NSP; ++sp)
            d[sp] += 1e-10f;
#pragma unroll
        for (int q = 0; q < 4; ++q) {
            const float prod = d[2 * q] * d[2 * q + 1];
            float rp;
            asm("rcp.approx.f32 %0, %1;" : "=f"(rp) : "f"(prod));
            wsp[2 * q]     = pi[2 * q]     * (rp * d[2 * q + 1]);
            wsp[2 * q + 1] = pi[2 * q + 1] * (rp * d[2 * q]);
        }
        {
            float r8;
            asm("rcp.approx.f32 %0, %1;" : "=f"(r8) : "f"(d[8]));
            wsp[8] = pi[8] * r8;
        }

        // out_k = a_k * sum_sp w_sp * p_sp[k]
        float o0 = 0.0f, o1 = 0.0f, o2 = 0.0f, o3 = 0.0f;
#pragma unroll
        for (int sp = 0; sp < NSP; ++sp) {
            o0 = fmaf(wsp[sp], p0[sp],  o0);
            o1 = fmaf(wsp[sp], p1v[sp], o1);
            o2 = fmaf(wsp[sp], p2[sp],  o2);
            o3 = fmaf(wsp[sp], p3[sp],  o3);
        }

        float* ob = out + base;
        ob[k0] = a0 * o0;
        ob[k1] = a1 * o1;
        ob[k2] = a2 * o2;
        if (last) ob[48] = a3 * o3;
    }
}

extern "C" void kernel_launch(void* const* d_in, const int* in_sizes, int n_in,
                              void* d_out, int out_size)
{
    const float* attn  = (const float*)d_in[0];
    const float* sims  = (const float*)d_in[1];
    const int*   sinds = (const int*)d_in[2];
    float*       out   = (float*)d_out;

    const int warps   = BB * HH * WW / 2;        // 16384 warps (2 pixels each)
    const int threads = 128;                     // 4 warps / CTA
    const int blocks  = warps / (threads / 32);  // 4096
    attn_reweight_kernel<<<blocks, threads>>>(attn, sims, sinds, out);
}

// round 6
// speedup vs baseline: 1.3223x; 1.3223x over previous
#include <cuda_runtime.h>

// Problem constants (fixed shapes)
#define BB   2
#define HD   4
#define HH   128
#define WW   128
#define KS   7
#define KK   49
#define NSP  9
#define SS   64
#define PLANE (HH * WW)

// Four pixels per warp: group g = lane>>3 handles pixel (h, w0+g).
// Lane t (=lane&7) owns k in {t, t+8, t+16, t+24, t+32, t+40}; t==0 also k=48.
// All reductions are 8-lane butterflies (xor 4,2,1) serving 4 pixels at once.
// No max-subtraction: the softmax-style ratio is scale-invariant in exp().
__global__ __launch_bounds__(128)
void attn_reweight_kernel(const float* __restrict__ attn,
                          const float* __restrict__ sims,
                          const int*   __restrict__ sinds,
                          float*       __restrict__ out)
{
    const int warpid = blockIdx.x * (blockDim.x >> 5) + (threadIdx.x >> 5);
    const int lane   = threadIdx.x & 31;
    const int g      = lane >> 3;        // pixel within warp
    const int t      = lane & 7;         // k-slot lane

    const int pix0 = warpid << 2;
    const int b    = pix0 >> 14;
    const int idx  = pix0 & 16383;
    const int h    = idx >> 7;
    const int w    = (idx & 127) + g;    // idx&127 is a multiple of 4

    const int hs = min(max(h - KS / 2, 0), HH - KS);
    const int ws = min(max(w - KS / 2, 0), WW - KS);

    // window offsets for k = 8j + t  (j = 0..5), plus k = 48 on t==0
    int off[6];
#pragma unroll
    for (int j = 0; j < 6; ++j) {
        const int k = 8 * j + t;
        off[j] = (hs + k / KS) * WW + ws + k % KS;
    }
    const int off6 = (hs + 6) * WW + (ws + 6);
    const bool l0  = (t == 0);

    // center position inside window (uniform per group)
    const int cidx  = (h - hs) * KS + (w - ws);       // [0,48]
    const int slotc = cidx >> 3;                      // 0..6
    const int srcl  = (g << 3) + (cidx & 7);

    const float* sb = sims + b * (SS * PLANE);

    // sinds: coalesced per-group loads, distribute via shfl
    const int sbase = (pix0 + g) * NSP;
    const int ind_a = __ldg(&sinds[sbase + t]);                  // sp = t (0..7)
    const int ind_b = l0 ? __ldg(&sinds[sbase + 8]) : 0;         // sp = 8

    // ---- gather 9 planes ----
    float p[6][NSP], p6[NSP];
#pragma unroll
    for (int sp = 0; sp < NSP; ++sp) {
        const int gid = (sp < 8) ? __shfl_sync(0xffffffffu, ind_a, (g << 3) + sp)
                                 : __shfl_sync(0xffffffffu, ind_b, (g << 3));
        const float* pl = sb + gid * PLANE;
#pragma unroll
        for (int j = 0; j < 6; ++j)
            p[j][sp] = __ldg(&pl[off[j]]);
        p6[sp] = l0 ? __ldg(&pl[off6]) : 0.0f;
    }

    // ---- pi via shfl from the window (center always inside) ----
    float pi[NSP];
#pragma unroll
    for (int sp = 0; sp < NSP; ++sp) {
        const float val = (slotc == 0) ? p[0][sp]
                        : (slotc == 1) ? p[1][sp]
                        : (slotc == 2) ? p[2][sp]
                        : (slotc == 3) ? p[3][sp]
                        : (slotc == 4) ? p[4][sp]
                        : (slotc == 5) ? p[5][sp] : p6[sp];
        pi[sp] = __shfl_sync(0xffffffffu, val, srcl);
    }

    // ---- per-head compute ----
#pragma unroll
    for (int hd = 0; hd < HD; ++hd) {
        const int base = (((b * HD + hd) * HH + h) * WW + w) * KK;
        const float* ab = attn + base;

        float a[6];
#pragma unroll
        for (int j = 0; j < 6; ++j)
            a[j] = __expf(__ldg(ab + 8 * j + t));
        const float a6 = __expf(l0 ? __ldg(ab + 48) : -1e30f);   // 0 on t!=0

        // d[sp] = sum_k a_k * p_sp[k]  (partial per lane, then 8-lane butterfly)
        float d[NSP];
#pragma unroll
        for (int sp = 0; sp < NSP; ++sp) {
            float acc = fmaf(a[0], p[0][sp], a6 * p6[sp]);
#pragma unroll
            for (int j = 1; j < 6; ++j)
                acc = fmaf(a[j], p[j][sp], acc);
            d[sp] = acc;
        }
#pragma unroll
        for (int o = 4; o > 0; o >>= 1) {
#pragma unroll
            for (int sp = 0; sp < NSP; ++sp)
                d[sp] += __shfl_xor_sync(0xffffffffu, d[sp], o);
        }

        // w_sp = pi_sp / (eps + d_sp); paired reciprocals: 5 MUFU for 9 divides
        float wsp[NSP];
#pragma unroll
        for (int sp = 0; sp < NSP; ++sp)
            d[sp] += 1e-10f;
#pragma unroll
        for (int q = 0; q < 4; ++q) {
            const float prod = d[2 * q] * d[2 * q + 1];
            float rp;
            asm("rcp.approx.f32 %0, %1;" : "=f"(rp) : "f"(prod));
            wsp[2 * q]     = pi[2 * q]     * (rp * d[2 * q + 1]);
            wsp[2 * q + 1] = pi[2 * q + 1] * (rp * d[2 * q]);
        }
        {
            float r8;
            asm("rcp.approx.f32 %0, %1;" : "=f"(r8) : "f"(d[8]));
            wsp[8] = pi[8] * r8;
        }

        // out_k = a_k * sum_sp w_sp * p_sp[k]
        float o6 = 0.0f;
        float o[6];
#pragma unroll
        for (int j = 0; j < 6; ++j) o[j] = 0.0f;
#pragma unroll
        for (int sp = 0; sp < NSP; ++sp) {
#pragma unroll
            for (int j = 0; j < 6; ++j)
                o[j] = fmaf(wsp[sp], p[j][sp], o[j]);
            o6 = fmaf(wsp[sp], p6[sp], o6);
        }

        float* ob = out + base;
#pragma unroll
        for (int j = 0; j < 6; ++j)
            ob[8 * j + t] = a[j] * o[j];
        if (l0) ob[48] = a6 * o6;
    }
}

extern "C" void kernel_launch(void* const* d_in, const int* in_sizes, int n_in,
                              void* d_out, int out_size)
{
    const float* attn  = (const float*)d_in[0];
    const float* sims  = (const float*)d_in[1];
    const int*   sinds = (const int*)d_in[2];
    float*       out   = (float*)d_out;

    const int warps   = BB * HH * WW / 4;        // 8192 warps (4 pixels each)
    const int threads = 128;                     // 4 warps / CTA
    const int blocks  = warps / (threads / 32);  // 2048
    attn_reweight_kernel<<<blocks, threads>>>(attn, sims, sinds, out);
}